// round 11
// baseline (speedup 1.0000x reference)
#include <cuda_runtime.h>
#include <math.h>

// Problem constants (fixed by setup_inputs)
#define BDIM 8
#define LDIM 1900
#define EDIM 256
#define HDIM 8
#define DDIM 32
#define MROWS (BDIM * LDIM)   // 15200
#define QKVW  (3 * EDIM)      // 768
#define PADSZ 1000
#define GRPW  200             // 2 * single_pad

typedef unsigned long long u64;

// ---- packed f32x2 helpers (Blackwell sm_103a) ------------------------------
__device__ __forceinline__ u64 pk2(float x, float y) {
    u64 d; asm("mov.b64 %0, {%1, %2};" : "=l"(d) : "f"(x), "f"(y)); return d;
}
__device__ __forceinline__ void upk2(float& x, float& y, u64 d) {
    asm("mov.b64 {%0, %1}, %2;" : "=f"(x), "=f"(y) : "l"(d));
}
__device__ __forceinline__ u64 ffma2(u64 a, u64 b, u64 c) {
    u64 d; asm("fma.rn.f32x2 %0, %1, %2, %3;" : "=l"(d) : "l"(a), "l"(b), "l"(c));
    return d;
}
__device__ __forceinline__ u64 fmul2(u64 a, u64 b) {
    u64 d; asm("mul.rn.f32x2 %0, %1, %2;" : "=l"(d) : "l"(a), "l"(b));
    return d;
}

// Scratch (static device globals; no cudaMalloc allowed)
__device__ float g_qkv[(size_t)MROWS * QKVW];   // 46.7 MB
__device__ float g_ctx[(size_t)MROWS * EDIM];   // 15.6 MB
__device__ float g_y  [(size_t)MROWS * EDIM];   // 15.6 MB

// ---------------------------------------------------------------------------
// f32x2 tiled SGEMM:  C[m,n] = sum_k A[m,k]*Bw[n,k] + bias[n] (+ resid[m,n])
// BM=128, BN=64, BK=32, 256 threads, per-thread 8m x 4n (16 FFMA2 / k).
// A tile stored DUPLICATED in SMEM so one LDS.64 yields an (a,a) pair.
// ---------------------------------------------------------------------------
#define AST 260   // As2 row stride (floats); even -> 8B-aligned pair loads
#define BST 68    // Bs row stride (floats); 16B-aligned float4 rows

template <bool RESID>
__global__ __launch_bounds__(256)
void gemm_bias_kernel(const float* __restrict__ A,
                      const float* __restrict__ Bw,
                      const float* __restrict__ bias,
                      const float* __restrict__ resid,
                      float* __restrict__ C,
                      int M, int N, int K)
{
    __shared__ float As2[32][AST];   // duplicated pairs: [k][2m],[k][2m+1]
    __shared__ float Bs [32][BST];

    const int tid = threadIdx.x;
    const int tx  = tid & 15;        // n: tx*4
    const int ty  = tid >> 4;        // m: ty*8
    const int m0  = blockIdx.y * 128;
    const int n0  = blockIdx.x * 64;

    u64 acc[8][2];
#pragma unroll
    for (int i = 0; i < 8; ++i) { acc[i][0] = 0ull; acc[i][1] = 0ull; }

    for (int k0 = 0; k0 < K; k0 += 32) {
        // A tile (128 x 32) -> transposed duplicated pairs
#pragma unroll
        for (int it = 0; it < 4; ++it) {
            int flat = tid + it * 256;            // 0..1023
            int row  = flat >> 3;                 // 0..127
            int k4   = (flat & 7) << 2;           // 0,4,...,28
            float4 v = make_float4(0.f, 0.f, 0.f, 0.f);
            if (m0 + row < M)
                v = *(const float4*)&A[(size_t)(m0 + row) * K + k0 + k4];
            *(float2*)&As2[k4 + 0][2 * row] = make_float2(v.x, v.x);
            *(float2*)&As2[k4 + 1][2 * row] = make_float2(v.y, v.y);
            *(float2*)&As2[k4 + 2][2 * row] = make_float2(v.z, v.z);
            *(float2*)&As2[k4 + 3][2 * row] = make_float2(v.w, v.w);
        }
        // B tile (64 x 32) -> transposed  (N multiple of 64)
#pragma unroll
        for (int it = 0; it < 2; ++it) {
            int flat = tid + it * 256;
            int row  = flat >> 3;
            int k4   = (flat & 7) << 2;
            float4 v = *(const float4*)&Bw[(size_t)(n0 + row) * K + k0 + k4];
            Bs[k4 + 0][row] = v.x;
            Bs[k4 + 1][row] = v.y;
            Bs[k4 + 2][row] = v.z;
            Bs[k4 + 3][row] = v.w;
        }
        __syncthreads();

#pragma unroll
        for (int k = 0; k < 32; ++k) {
            ulonglong2 b = *(const ulonglong2*)&Bs[k][tx * 4];
            u64 a2[8];
#pragma unroll
            for (int i = 0; i < 8; ++i)
                a2[i] = *(const u64*)&As2[k][2 * (ty * 8 + i)];
#pragma unroll
            for (int i = 0; i < 8; ++i) {
                acc[i][0] = ffma2(a2[i], b.x, acc[i][0]);
                acc[i][1] = ffma2(a2[i], b.y, acc[i][1]);
            }
        }
        __syncthreads();
    }

    const float4 b4 = *(const float4*)&bias[n0 + tx * 4];
#pragma unroll
    for (int i = 0; i < 8; ++i) {
        int m = m0 + ty * 8 + i;
        if (m >= M) continue;
        float c0, c1, c2, c3;
        upk2(c0, c1, acc[i][0]);
        upk2(c2, c3, acc[i][1]);
        float4 v;
        v.x = c0 + b4.x; v.y = c1 + b4.y; v.z = c2 + b4.z; v.w = c3 + b4.w;
        if (RESID) {
            float4 r4 = *(const float4*)&resid[(size_t)m * N + n0 + tx * 4];
            v.x += r4.x; v.y += r4.y; v.z += r4.z; v.w += r4.w;
        }
        *(float4*)&C[(size_t)m * N + n0 + tx * 4] = v;
    }
}

// ---------------------------------------------------------------------------
// Flash attention with DN mask, f32x2 inner products. One thread = one query.
// Visible columns for row l:
//   l <  1000 : [g*200, g*200+200)  (g = l/200)   plus  [1000, 1900)
//   l >= 1000 : [1000, 1900)
// ---------------------------------------------------------------------------
__global__ __launch_bounds__(128)
void attn_kernel(const float* __restrict__ qkv, float* __restrict__ ctx)
{
    const int tile = blockIdx.x;                  // 0..14
    const int h    = blockIdx.y;
    const int b    = blockIdx.z;
    const int tid  = threadIdx.x;                 // 128
    const int l    = tile * 128 + tid;
    const bool valid = (l < LDIM);

    __shared__ float Qs[128][DDIM + 2];           // stride 34: 8B-aligned pairs
    __shared__ float Ks[64][DDIM];                // 16B-aligned rows
    __shared__ float Vs[64][DDIM];

    const size_t baseQ = (size_t)b * LDIM * QKVW + (size_t)h * DDIM;
    const size_t baseK = baseQ + EDIM;
    const size_t baseV = baseQ + 2 * EDIM;

    // Coalesced staging of the Q tile, then pull own row to packed registers
    for (int i = tid; i < 128 * DDIM; i += 128) {
        int r = i >> 5, c = i & 31;
        int lr = tile * 128 + r;
        Qs[r][c] = (lr < LDIM) ? qkv[baseQ + (size_t)lr * QKVW + c] : 0.f;
    }
    __syncthreads();

    u64 q2[16], o2[16];
#pragma unroll
    for (int t = 0; t < 16; ++t) {
        q2[t] = *(const u64*)&Qs[tid][2 * t];
        o2[t] = 0ull;
    }
    float mrow = -3.0e38f;
    float lsum = 0.f;
    const float scale = 0.17677669529663689f;     // 1/sqrt(32)

    // Block-level DN column range (union over rows in this tile)
    const int l0  = tile * 128;
    const int lmx = (l0 + 127 < LDIM - 1) ? (l0 + 127) : (LDIM - 1);
    int Astart = 0, Aend = 0;
    if (l0 < PADSZ) {
        int gmin = l0 / GRPW;
        int gmax = ((lmx < PADSZ - 1) ? lmx : (PADSZ - 1)) / GRPW;
        Astart = gmin * GRPW;
        Aend   = (gmax + 1) * GRPW;               // <= 1000
    }
    const int myglo = (l / GRPW) * GRPW;          // meaningful only when l < 1000

#pragma unroll 1
    for (int pass = 0; pass < 2; ++pass) {
        const int cs = (pass == 0) ? Astart : PADSZ;
        const int ce = (pass == 0) ? Aend   : LDIM;
#pragma unroll 1
        for (int m0c = cs; m0c < ce; m0c += 64) {
            const int cols = (ce - m0c < 64) ? (ce - m0c) : 64;
            __syncthreads();
            for (int i = tid; i < cols * DDIM; i += 128) {
                int r = i >> 5, c = i & 31;
                size_t off = (size_t)(m0c + r) * QKVW + c;
                Ks[r][c] = qkv[baseK + off];
                Vs[r][c] = qkv[baseV + off];
            }
            __syncthreads();

            if (valid) {
                int jlo = 0, jhi = cols;
                if (pass == 0) {
                    if (l >= PADSZ) {
                        jhi = 0;
                    } else {
                        int a = myglo - m0c;             if (a > 0) jlo = a;
                        int bnd = myglo + GRPW - m0c;    if (bnd < jhi) jhi = bnd;
                    }
                }
                for (int j = jlo; j < jhi; ++j) {
                    u64 s2 = 0ull;
#pragma unroll
                    for (int t = 0; t < 8; ++t) {
                        ulonglong2 kk = *(const ulonglong2*)&Ks[j][4 * t];
                        s2 = ffma2(q2[2 * t + 0], kk.x, s2);
                        s2 = ffma2(q2[2 * t + 1], kk.y, s2);
                    }
                    float slo, shi;
                    upk2(slo, shi, s2);
                    float s = (slo + shi) * scale;

                    if (s > mrow) {
                        float corr = __expf(mrow - s);
                        lsum *= corr;
                        u64 c2 = pk2(corr, corr);
#pragma unroll
                        for (int t = 0; t < 16; ++t) o2[t] = fmul2(o2[t], c2);
                        mrow = s;
                    }
                    float p = __expf(s - mrow);
                    lsum += p;
                    u64 p2 = pk2(p, p);
#pragma unroll
                    for (int t = 0; t < 8; ++t) {
                        ulonglong2 vv = *(const ulonglong2*)&Vs[j][4 * t];
                        o2[2 * t + 0] = ffma2(p2, vv.x, o2[2 * t + 0]);
                        o2[2 * t + 1] = ffma2(p2, vv.y, o2[2 * t + 1]);
                    }
                }
            }
        }
    }

    // Normalize and write out (staged through SMEM for coalescing)
    const float inv = valid ? (1.f / lsum) : 0.f;
    const u64 inv2 = pk2(inv, inv);
    __syncthreads();
#pragma unroll
    for (int t = 0; t < 16; ++t) {
        float lo, hi;
        upk2(lo, hi, fmul2(o2[t], inv2));
        *(float2*)&Qs[tid][2 * t] = make_float2(lo, hi);
    }
    __syncthreads();
    for (int i = tid; i < 128 * DDIM; i += 128) {
        int r = i >> 5, c = i & 31;
        int lr = tile * 128 + r;
        if (lr < LDIM)
            ctx[((size_t)b * LDIM + lr) * EDIM + (size_t)h * DDIM + c] = Qs[r][c];
    }
}

// ---------------------------------------------------------------------------
// LayerNorm: one warp per row of 256.
// ---------------------------------------------------------------------------
__global__ __launch_bounds__(256)
void ln_kernel(const float* __restrict__ y,
               const float* __restrict__ g,
               const float* __restrict__ bt,
               float* __restrict__ out)
{
    const int row  = blockIdx.x * 8 + (threadIdx.x >> 5);
    const int lane = threadIdx.x & 31;
    if (row >= MROWS) return;

    const float* yr = y + (size_t)row * EDIM;
    float4 v0 = ((const float4*)yr)[lane];
    float4 v1 = ((const float4*)yr)[lane + 32];

    float s  = v0.x + v0.y + v0.z + v0.w + v1.x + v1.y + v1.z + v1.w;
    float ss = v0.x * v0.x + v0.y * v0.y + v0.z * v0.z + v0.w * v0.w
             + v1.x * v1.x + v1.y * v1.y + v1.z * v1.z + v1.w * v1.w;
#pragma unroll
    for (int off = 16; off; off >>= 1) {
        s  += __shfl_xor_sync(0xFFFFFFFFu, s,  off);
        ss += __shfl_xor_sync(0xFFFFFFFFu, ss, off);
    }
    const float mu  = s * (1.f / EDIM);
    const float var = ss * (1.f / EDIM) - mu * mu;
    const float r   = rsqrtf(var + 1e-5f);

    float* orow = out + (size_t)row * EDIM;
    float4 g0 = ((const float4*)g)[lane];
    float4 g1 = ((const float4*)g)[lane + 32];
    float4 b0 = ((const float4*)bt)[lane];
    float4 b1 = ((const float4*)bt)[lane + 32];

    float4 o0, o1;
    o0.x = (v0.x - mu) * r * g0.x + b0.x;
    o0.y = (v0.y - mu) * r * g0.y + b0.y;
    o0.z = (v0.z - mu) * r * g0.z + b0.z;
    o0.w = (v0.w - mu) * r * g0.w + b0.w;
    o1.x = (v1.x - mu) * r * g1.x + b1.x;
    o1.y = (v1.y - mu) * r * g1.y + b1.y;
    o1.z = (v1.z - mu) * r * g1.z + b1.z;
    o1.w = (v1.w - mu) * r * g1.w + b1.w;
    *(float4*)&orow[lane * 4]       = o0;
    *(float4*)&orow[128 + lane * 4] = o1;
}

// ---------------------------------------------------------------------------
extern "C" void kernel_launch(void* const* d_in, const int* in_sizes, int n_in,
                              void* d_out, int out_size)
{
    const float* x     = (const float*)d_in[0];
    const float* in_w  = (const float*)d_in[1];
    const float* in_b  = (const float*)d_in[2];
    const float* out_w = (const float*)d_in[3];
    const float* out_b = (const float*)d_in[4];
    const float* ln_g  = (const float*)d_in[5];
    const float* ln_b  = (const float*)d_in[6];
    float* out = (float*)d_out;

    void *p_qkv = nullptr, *p_ctx = nullptr, *p_y = nullptr;
    cudaGetSymbolAddress(&p_qkv, g_qkv);
    cudaGetSymbolAddress(&p_ctx, g_ctx);
    cudaGetSymbolAddress(&p_y,   g_y);
    float* qkv = (float*)p_qkv;
    float* ctx = (float*)p_ctx;
    float* yy  = (float*)p_y;

    // 1) QKV projection: [15200,256] x [768,256]^T -> [15200,768]
    {
        dim3 grid(QKVW / 64, (MROWS + 127) / 128);
        gemm_bias_kernel<false><<<grid, 256>>>(x, in_w, in_b, nullptr, qkv,
                                               MROWS, QKVW, EDIM);
    }
    // 2) Masked flash attention -> ctx [15200,256]
    {
        dim3 grid((LDIM + 127) / 128, HDIM, BDIM);
        attn_kernel<<<grid, 128>>>(qkv, ctx);
    }
    // 3) Out projection + bias + residual: y = ctx @ out_w^T + out_b + x
    {
        dim3 grid(EDIM / 64, (MROWS + 127) / 128);
        gemm_bias_kernel<true><<<grid, 256>>>(ctx, out_w, out_b, x, yy,
                                              MROWS, EDIM, EDIM);
    }
    // 4) LayerNorm -> d_out
    {
        ln_kernel<<<MROWS / 8, 256>>>(yy, ln_g, ln_b, out);
    }
}

// round 12
// speedup vs baseline: 1.0018x; 1.0018x over previous
#include <cuda_runtime.h>
#include <math.h>

// Problem constants (fixed by setup_inputs)
#define BDIM 8
#define LDIM 1900
#define EDIM 256
#define HDIM 8
#define DDIM 32
#define MROWS (BDIM * LDIM)   // 15200
#define QKVW  (3 * EDIM)      // 768
#define PADSZ 1000
#define GRPW  200             // 2 * single_pad

typedef unsigned long long u64;

// ---- packed f32x2 helpers (Blackwell sm_103a) ------------------------------
__device__ __forceinline__ u64 pk2(float x, float y) {
    u64 d; asm("mov.b64 %0, {%1, %2};" : "=l"(d) : "f"(x), "f"(y)); return d;
}
__device__ __forceinline__ void upk2(float& x, float& y, u64 d) {
    asm("mov.b64 {%0, %1}, %2;" : "=f"(x), "=f"(y) : "l"(d));
}
__device__ __forceinline__ u64 ffma2(u64 a, u64 b, u64 c) {
    u64 d; asm("fma.rn.f32x2 %0, %1, %2, %3;" : "=l"(d) : "l"(a), "l"(b), "l"(c));
    return d;
}
__device__ __forceinline__ u64 fmul2(u64 a, u64 b) {
    u64 d; asm("mul.rn.f32x2 %0, %1, %2;" : "=l"(d) : "l"(a), "l"(b));
    return d;
}

// Scratch (static device globals; no cudaMalloc allowed)
__device__ float g_qkv[(size_t)MROWS * QKVW];   // 46.7 MB
__device__ float g_ctx[(size_t)MROWS * EDIM];   // 15.6 MB
__device__ float g_y  [(size_t)MROWS * EDIM];   // 15.6 MB

// ---------------------------------------------------------------------------
// f32x2 tiled SGEMM:  C[m,n] = sum_k A[m,k]*Bw[n,k] + bias[n] (+ resid[m,n])
// BM=128, BN=64, BK=32, 256 threads, per-thread 8m x 4n (16 FFMA2 / k).
// A tile stored DUPLICATED in SMEM so one LDS.64 yields an (a,a) pair.
// ---------------------------------------------------------------------------
#define AST 260   // As2 row stride (floats); even -> 8B-aligned pair loads
#define BST 68    // Bs row stride (floats); 16B-aligned float4 rows

template <bool RESID>
__global__ __launch_bounds__(256)
void gemm_bias_kernel(const float* __restrict__ A,
                      const float* __restrict__ Bw,
                      const float* __restrict__ bias,
                      const float* __restrict__ resid,
                      float* __restrict__ C,
                      int M, int N, int K)
{
    __shared__ float As2[32][AST];   // duplicated pairs: [k][2m],[k][2m+1]
    __shared__ float Bs [32][BST];

    const int tid = threadIdx.x;
    const int tx  = tid & 15;        // n: tx*4
    const int ty  = tid >> 4;        // m: ty*8
    const int m0  = blockIdx.y * 128;
    const int n0  = blockIdx.x * 64;

    u64 acc[8][2];
#pragma unroll
    for (int i = 0; i < 8; ++i) { acc[i][0] = 0ull; acc[i][1] = 0ull; }

    for (int k0 = 0; k0 < K; k0 += 32) {
        // A tile (128 x 32) -> transposed duplicated pairs
#pragma unroll
        for (int it = 0; it < 4; ++it) {
            int flat = tid + it * 256;            // 0..1023
            int row  = flat >> 3;                 // 0..127
            int k4   = (flat & 7) << 2;           // 0,4,...,28
            float4 v = make_float4(0.f, 0.f, 0.f, 0.f);
            if (m0 + row < M)
                v = *(const float4*)&A[(size_t)(m0 + row) * K + k0 + k4];
            *(float2*)&As2[k4 + 0][2 * row] = make_float2(v.x, v.x);
            *(float2*)&As2[k4 + 1][2 * row] = make_float2(v.y, v.y);
            *(float2*)&As2[k4 + 2][2 * row] = make_float2(v.z, v.z);
            *(float2*)&As2[k4 + 3][2 * row] = make_float2(v.w, v.w);
        }
        // B tile (64 x 32) -> transposed  (N multiple of 64)
#pragma unroll
        for (int it = 0; it < 2; ++it) {
            int flat = tid + it * 256;
            int row  = flat >> 3;
            int k4   = (flat & 7) << 2;
            float4 v = *(const float4*)&Bw[(size_t)(n0 + row) * K + k0 + k4];
            Bs[k4 + 0][row] = v.x;
            Bs[k4 + 1][row] = v.y;
            Bs[k4 + 2][row] = v.z;
            Bs[k4 + 3][row] = v.w;
        }
        __syncthreads();

#pragma unroll
        for (int k = 0; k < 32; ++k) {
            ulonglong2 b = *(const ulonglong2*)&Bs[k][tx * 4];
            u64 a2[8];
#pragma unroll
            for (int i = 0; i < 8; ++i)
                a2[i] = *(const u64*)&As2[k][2 * (ty * 8 + i)];
#pragma unroll
            for (int i = 0; i < 8; ++i) {
                acc[i][0] = ffma2(a2[i], b.x, acc[i][0]);
                acc[i][1] = ffma2(a2[i], b.y, acc[i][1]);
            }
        }
        __syncthreads();
    }

    const float4 b4 = *(const float4*)&bias[n0 + tx * 4];
#pragma unroll
    for (int i = 0; i < 8; ++i) {
        int m = m0 + ty * 8 + i;
        if (m >= M) continue;
        float c0, c1, c2, c3;
        upk2(c0, c1, acc[i][0]);
        upk2(c2, c3, acc[i][1]);
        float4 v;
        v.x = c0 + b4.x; v.y = c1 + b4.y; v.z = c2 + b4.z; v.w = c3 + b4.w;
        if (RESID) {
            float4 r4 = *(const float4*)&resid[(size_t)m * N + n0 + tx * 4];
            v.x += r4.x; v.y += r4.y; v.z += r4.z; v.w += r4.w;
        }
        *(float4*)&C[(size_t)m * N + n0 + tx * 4] = v;
    }
}

// ---------------------------------------------------------------------------
// Flash attention with DN mask, f32x2 inner products. One thread = one query.
// Visible columns for row l:
//   l <  1000 : [g*200, g*200+200)  (g = l/200)   plus  [1000, 1900)
//   l >= 1000 : [1000, 1900)
// ---------------------------------------------------------------------------
__global__ __launch_bounds__(128)
void attn_kernel(const float* __restrict__ qkv, float* __restrict__ ctx)
{
    const int tile = blockIdx.x;                  // 0..14
    const int h    = blockIdx.y;
    const int b    = blockIdx.z;
    const int tid  = threadIdx.x;                 // 128
    const int l    = tile * 128 + tid;
    const bool valid = (l < LDIM);

    __shared__ float Qs[128][DDIM + 2];           // stride 34: 8B-aligned pairs
    __shared__ float Ks[64][DDIM];                // 16B-aligned rows
    __shared__ float Vs[64][DDIM];

    const size_t baseQ = (size_t)b * LDIM * QKVW + (size_t)h * DDIM;
    const size_t baseK = baseQ + EDIM;
    const size_t baseV = baseQ + 2 * EDIM;

    // Coalesced staging of the Q tile, then pull own row to packed registers
    for (int i = tid; i < 128 * DDIM; i += 128) {
        int r = i >> 5, c = i & 31;
        int lr = tile * 128 + r;
        Qs[r][c] = (lr < LDIM) ? qkv[baseQ + (size_t)lr * QKVW + c] : 0.f;
    }
    __syncthreads();

    u64 q2[16], o2[16];
#pragma unroll
    for (int t = 0; t < 16; ++t) {
        q2[t] = *(const u64*)&Qs[tid][2 * t];
        o2[t] = 0ull;
    }
    float mrow = -3.0e38f;
    float lsum = 0.f;
    const float scale = 0.17677669529663689f;     // 1/sqrt(32)

    // Block-level DN column range (union over rows in this tile)
    const int l0  = tile * 128;
    const int lmx = (l0 + 127 < LDIM - 1) ? (l0 + 127) : (LDIM - 1);
    int Astart = 0, Aend = 0;
    if (l0 < PADSZ) {
        int gmin = l0 / GRPW;
        int gmax = ((lmx < PADSZ - 1) ? lmx : (PADSZ - 1)) / GRPW;
        Astart = gmin * GRPW;
        Aend   = (gmax + 1) * GRPW;               // <= 1000
    }
    const int myglo = (l / GRPW) * GRPW;          // meaningful only when l < 1000

#pragma unroll 1
    for (int pass = 0; pass < 2; ++pass) {
        const int cs = (pass == 0) ? Astart : PADSZ;
        const int ce = (pass == 0) ? Aend   : LDIM;
#pragma unroll 1
        for (int m0c = cs; m0c < ce; m0c += 64) {
            const int cols = (ce - m0c < 64) ? (ce - m0c) : 64;
            __syncthreads();
            for (int i = tid; i < cols * DDIM; i += 128) {
                int r = i >> 5, c = i & 31;
                size_t off = (size_t)(m0c + r) * QKVW + c;
                Ks[r][c] = qkv[baseK + off];
                Vs[r][c] = qkv[baseV + off];
            }
            __syncthreads();

            if (valid) {
                int jlo = 0, jhi = cols;
                if (pass == 0) {
                    if (l >= PADSZ) {
                        jhi = 0;
                    } else {
                        int a = myglo - m0c;             if (a > 0) jlo = a;
                        int bnd = myglo + GRPW - m0c;    if (bnd < jhi) jhi = bnd;
                    }
                }
                for (int j = jlo; j < jhi; ++j) {
                    u64 s2 = 0ull;
#pragma unroll
                    for (int t = 0; t < 8; ++t) {
                        ulonglong2 kk = *(const ulonglong2*)&Ks[j][4 * t];
                        s2 = ffma2(q2[2 * t + 0], kk.x, s2);
                        s2 = ffma2(q2[2 * t + 1], kk.y, s2);
                    }
                    float slo, shi;
                    upk2(slo, shi, s2);
                    float s = (slo + shi) * scale;

                    if (s > mrow) {
                        float corr = __expf(mrow - s);
                        lsum *= corr;
                        u64 c2 = pk2(corr, corr);
#pragma unroll
                        for (int t = 0; t < 16; ++t) o2[t] = fmul2(o2[t], c2);
                        mrow = s;
                    }
                    float p = __expf(s - mrow);
                    lsum += p;
                    u64 p2 = pk2(p, p);
#pragma unroll
                    for (int t = 0; t < 8; ++t) {
                        ulonglong2 vv = *(const ulonglong2*)&Vs[j][4 * t];
                        o2[2 * t + 0] = ffma2(p2, vv.x, o2[2 * t + 0]);
                        o2[2 * t + 1] = ffma2(p2, vv.y, o2[2 * t + 1]);
                    }
                }
            }
        }
    }

    // Normalize and write out (staged through SMEM for coalescing)
    const float inv = valid ? (1.f / lsum) : 0.f;
    const u64 inv2 = pk2(inv, inv);
    __syncthreads();
#pragma unroll
    for (int t = 0; t < 16; ++t) {
        float lo, hi;
        upk2(lo, hi, fmul2(o2[t], inv2));
        *(float2*)&Qs[tid][2 * t] = make_float2(lo, hi);
    }
    __syncthreads();
    for (int i = tid; i < 128 * DDIM; i += 128) {
        int r = i >> 5, c = i & 31;
        int lr = tile * 128 + r;
        if (lr < LDIM)
            ctx[((size_t)b * LDIM + lr) * EDIM + (size_t)h * DDIM + c] = Qs[r][c];
    }
}

// ---------------------------------------------------------------------------
// LayerNorm: one warp per row of 256.
// ---------------------------------------------------------------------------
__global__ __launch_bounds__(256)
void ln_kernel(const float* __restrict__ y,
               const float* __restrict__ g,
               const float* __restrict__ bt,
               float* __restrict__ out)
{
    const int row  = blockIdx.x * 8 + (threadIdx.x >> 5);
    const int lane = threadIdx.x & 31;
    if (row >= MROWS) return;

    const float* yr = y + (size_t)row * EDIM;
    float4 v0 = ((const float4*)yr)[lane];
    float4 v1 = ((const float4*)yr)[lane + 32];

    float s  = v0.x + v0.y + v0.z + v0.w + v1.x + v1.y + v1.z + v1.w;
    float ss = v0.x * v0.x + v0.y * v0.y + v0.z * v0.z + v0.w * v0.w
             + v1.x * v1.x + v1.y * v1.y + v1.z * v1.z + v1.w * v1.w;
#pragma unroll
    for (int off = 16; off; off >>= 1) {
        s  += __shfl_xor_sync(0xFFFFFFFFu, s,  off);
        ss += __shfl_xor_sync(0xFFFFFFFFu, ss, off);
    }
    const float mu  = s * (1.f / EDIM);
    const float var = ss * (1.f / EDIM) - mu * mu;
    const float r   = rsqrtf(var + 1e-5f);

    float* orow = out + (size_t)row * EDIM;
    float4 g0 = ((const float4*)g)[lane];
    float4 g1 = ((const float4*)g)[lane + 32];
    float4 b0 = ((const float4*)bt)[lane];
    float4 b1 = ((const float4*)bt)[lane + 32];

    float4 o0, o1;
    o0.x = (v0.x - mu) * r * g0.x + b0.x;
    o0.y = (v0.y - mu) * r * g0.y + b0.y;
    o0.z = (v0.z - mu) * r * g0.z + b0.z;
    o0.w = (v0.w - mu) * r * g0.w + b0.w;
    o1.x = (v1.x - mu) * r * g1.x + b1.x;
    o1.y = (v1.y - mu) * r * g1.y + b1.y;
    o1.z = (v1.z - mu) * r * g1.z + b1.z;
    o1.w = (v1.w - mu) * r * g1.w + b1.w;
    *(float4*)&orow[lane * 4]       = o0;
    *(float4*)&orow[128 + lane * 4] = o1;
}

// ---------------------------------------------------------------------------
extern "C" void kernel_launch(void* const* d_in, const int* in_sizes, int n_in,
                              void* d_out, int out_size)
{
    const float* x     = (const float*)d_in[0];
    const float* in_w  = (const float*)d_in[1];
    const float* in_b  = (const float*)d_in[2];
    const float* out_w = (const float*)d_in[3];
    const float* out_b = (const float*)d_in[4];
    const float* ln_g  = (const float*)d_in[5];
    const float* ln_b  = (const float*)d_in[6];
    float* out = (float*)d_out;

    void *p_qkv = nullptr, *p_ctx = nullptr, *p_y = nullptr;
    cudaGetSymbolAddress(&p_qkv, g_qkv);
    cudaGetSymbolAddress(&p_ctx, g_ctx);
    cudaGetSymbolAddress(&p_y,   g_y);
    float* qkv = (float*)p_qkv;
    float* ctx = (float*)p_ctx;
    float* yy  = (float*)p_y;

    // 1) QKV projection: [15200,256] x [768,256]^T -> [15200,768]
    {
        dim3 grid(QKVW / 64, (MROWS + 127) / 128);
        gemm_bias_kernel<false><<<grid, 256>>>(x, in_w, in_b, nullptr, qkv,
                                               MROWS, QKVW, EDIM);
    }
    // 2) Masked flash attention -> ctx [15200,256]
    {
        dim3 grid((LDIM + 127) / 128, HDIM, BDIM);
        attn_kernel<<<grid, 128>>>(qkv, ctx);
    }
    // 3) Out projection + bias + residual: y = ctx @ out_w^T + out_b + x
    {
        dim3 grid(EDIM / 64, (MROWS + 127) / 128);
        gemm_bias_kernel<true><<<grid, 256>>>(ctx, out_w, out_b, x, yy,
                                              MROWS, EDIM, EDIM);
    }
    // 4) LayerNorm -> d_out
    {
        ln_kernel<<<MROWS / 8, 256>>>(yy, ln_g, ln_b, out);
    }
}